// round 7
// baseline (speedup 1.0000x reference)
#include <cuda_runtime.h>
#include <cuda_fp16.h>
#include <string.h>

// Problem constants
#define B_TOTAL 65536
#define CN 16
#define CC 16
#define DIM 128
#define VOC 65
#define EPSF 1e-5f

// Decomposition: D=128 in 2 chunks of 64. One warp handles TWO rows per
// iteration: lanes 0-15 -> row A, lanes 16-31 -> row B. Each lane owns a
// 4-element (8B fp16) slice of its row's 64-wide chunk.
// Software pipeline: LDGs for iteration i+1 issue before consuming iteration i.
#define DCH 64
#define NCHUNK 2
#define NBX 74            // 74 * 2 = 148 CTAs = one per SM
#define NTHREADS 1024
#define NWARPS 32
#define STEP (2 * NWARPS)

// Shared memory:
//   emb_s : CC*VOC*DCH halves = 66560 halves = 133120 B (fp16 table chunk)
//   slots : per-warp double-buffered: 2 bufs x 256 B = 512 B/warp -> 16384 B
#define EMB_HALVES (CC * VOC * DCH)
#define SLOTS_BYTES (NWARPS * 512)
#define SMEM_BYTES (EMB_HALVES * 2 + SLOTS_BYTES)

__device__ __forceinline__ __half2 u2h2(unsigned u) {
    __half2 h; memcpy(&h, &u, 4); return h;
}

__global__ __launch_bounds__(NTHREADS, 1)
void embed_att_kernel(const float* __restrict__ x_num,
                      const float* __restrict__ means,
                      const float* __restrict__ stds,
                      const float* __restrict__ lin_W,
                      const float* __restrict__ lin_b,
                      const float* __restrict__ emb,
                      const int*   __restrict__ x_cat,
                      float*       __restrict__ out)
{
    extern __shared__ __align__(16) char smem_raw[];
    __half* emb_s = (__half*)smem_raw;
    char*   slots = smem_raw + EMB_HALVES * 2;

    const int tid   = threadIdx.x;
    const int lane  = tid & 31;
    const int wrp   = tid >> 5;
    const int sub   = lane & 15;   // attr index (producer) / 16B slice owner
    const int grp   = lane >> 4;   // 0 = row A, 1 = row B
    const int chunk = blockIdx.y;
    const int dbase = chunk * DCH;

    // ---- Preload emb chunk into SMEM as fp16 (1040 vectors x 128B) ----
    for (int s = tid; s < CC * VOC * (DCH / 4); s += NTHREADS) {
        int vec = s >> 4;
        int jj  = (s & 15) * 4;
        float4 f = *(const float4*)(emb + (size_t)vec * DIM + dbase + jj);
        *(__half2*)(emb_s + vec * DCH + jj)     = __floats2half2_rn(f.x, f.y);
        *(__half2*)(emb_s + vec * DCH + jj + 2) = __floats2half2_rn(f.z, f.w);
    }

    // ---- Per-lane constants ----
    const float invr = 1.0f / (stds[sub] + EPSF);
    const float c0   = -means[sub] * invr;
    const int   voff_bytes = sub * VOC * DCH * 2;   // byte base for attr 'sub'

    // W slice (4 floats per attr) as 2x half2; bias pre-summed then fp16
    __half2 wa[CN], wb[CN];
    float4 bias = make_float4(0.f, 0.f, 0.f, 0.f);
    #pragma unroll
    for (int i = 0; i < CN; i++) {
        float4 wf = *(const float4*)(lin_W + i * DIM + dbase + 4 * sub);
        wa[i] = __floats2half2_rn(wf.x, wf.y);
        wb[i] = __floats2half2_rn(wf.z, wf.w);
        float4 lb = *(const float4*)(lin_b + i * DIM + dbase + 4 * sub);
        bias.x += lb.x; bias.y += lb.y; bias.z += lb.z; bias.w += lb.w;
    }
    const __half2 bha = __floats2half2_rn(bias.x, bias.y);
    const __half2 bhb = __floats2half2_rn(bias.z, bias.w);
    __syncthreads();

    // ---- Balanced row range ----
    const int bx    = blockIdx.x;
    const int start = (int)(((long long)bx       * B_TOTAL) / NBX);
    const int end   = (int)(((long long)(bx + 1) * B_TOTAL) / NBX);

    char* wslot = slots + wrp * 512;
    const char* myemb = (const char*)emb_s + 8 * sub;  // lane's 8B slice base
    const int slot_off = (sub >> 1) * 32 + grp * 16 + (sub & 1) * 8;

    const __half2 h2z = __float2half2_rn(0.f);

    int b = start + wrp * 2;

    // ---- Prologue: load + produce iteration 0 into buf 0 ----
    float xc = 0.f; int vc = 0;
    {
        int r = b + grp;
        if (r < end) {
            xc = __ldg(x_num + r * CN + sub);
            vc = __ldg(x_cat + r * CC + sub);
        }
    }
    {
        float t = fmaf(xc, invr, c0);
        float z = __fdividef(1.0f, 1.0f + __expf(-t));
        __half2 zz = __floats2half2_rn(z, z);
        int zb; memcpy(&zb, &zz, 4);
        *(int2*)(wslot + slot_off) = make_int2(voff_bytes + vc * (DCH * 2), zb);
    }
    int buf = 0;

    for (; b < end; b += STEP) {
        // ---- Prefetch iteration i+1 global loads (off the critical path) ----
        float xn = 0.f; int vn = 0;
        {
            int nr = b + STEP + grp;
            if (nr < end) {
                xn = __ldg(x_num + nr * CN + sub);
                vn = __ldg(x_cat + nr * CC + sub);
            }
        }

        __syncwarp();   // buf's slots (written last iteration) now visible

        // ---- Consume buf: 8 slot broadcasts x {2 gathers + 2 numeric attrs} ----
        const int4* sl = (const int4*)(wslot + buf * 256 + grp * 16);
        __half2 g00 = bha, g01 = bhb, g10 = h2z, g11 = h2z;
        __half2 n0 = h2z, n1 = h2z;
        #pragma unroll
        for (int e4 = 0; e4 < 8; e4++) {
            int4 p = sl[e4 * 2];                       // {off0,z0,off1,z1} bytes
            uint2 q0 = *(const uint2*)(myemb + p.x);   // LDS.64 gather
            uint2 q1 = *(const uint2*)(myemb + p.z);
            __half2 zh0 = u2h2((unsigned)p.y);
            __half2 zh1 = u2h2((unsigned)p.w);
            if (e4 < 4) {
                g00 = __hadd2(g00, u2h2(q0.x)); g01 = __hadd2(g01, u2h2(q0.y));
                g00 = __hadd2(g00, u2h2(q1.x)); g01 = __hadd2(g01, u2h2(q1.y));
            } else {
                g10 = __hadd2(g10, u2h2(q0.x)); g11 = __hadd2(g11, u2h2(q0.y));
                g10 = __hadd2(g10, u2h2(q1.x)); g11 = __hadd2(g11, u2h2(q1.y));
            }
            n0 = __hfma2(zh0, wa[2 * e4],     n0);
            n1 = __hfma2(zh0, wb[2 * e4],     n1);
            n0 = __hfma2(zh1, wa[2 * e4 + 1], n0);
            n1 = __hfma2(zh1, wb[2 * e4 + 1], n1);
        }

        __half2 s0 = __hadd2(__hadd2(g00, g10), n0);
        __half2 s1 = __hadd2(__hadd2(g01, g11), n1);
        float2 f0 = __half22float2(s0);
        float2 f1 = __half22float2(s1);
        int myrow = b + grp;
        if (myrow < end) {
            *(float4*)(out + (size_t)myrow * DIM + dbase + 4 * sub) =
                make_float4(f0.x, f0.y, f1.x, f1.y);
        }

        // ---- Produce iteration i+1 into buf^1 (LDGs already landed) ----
        {
            float t = fmaf(xn, invr, c0);
            float z = __fdividef(1.0f, 1.0f + __expf(-t));
            __half2 zz = __floats2half2_rn(z, z);
            int zb; memcpy(&zb, &zz, 4);
            *(int2*)(wslot + (buf ^ 1) * 256 + slot_off) =
                make_int2(voff_bytes + vn * (DCH * 2), zb);
        }
        buf ^= 1;
    }
}

extern "C" void kernel_launch(void* const* d_in, const int* in_sizes, int n_in,
                              void* d_out, int out_size)
{
    const float* x_num = (const float*)d_in[0];
    const float* means = (const float*)d_in[1];
    const float* stds  = (const float*)d_in[2];
    const float* lin_W = (const float*)d_in[3];
    const float* lin_b = (const float*)d_in[4];
    const float* emb   = (const float*)d_in[5];
    const int*   x_cat = (const int*)d_in[6];
    float* out = (float*)d_out;

    cudaFuncSetAttribute(embed_att_kernel,
                         cudaFuncAttributeMaxDynamicSharedMemorySize, SMEM_BYTES);

    dim3 grid(NBX, NCHUNK);
    embed_att_kernel<<<grid, NTHREADS, SMEM_BYTES>>>(
        x_num, means, stds, lin_W, lin_b, emb, x_cat, out);
}